// round 13
// baseline (speedup 1.0000x reference)
#include <cuda_runtime.h>
#include <cuda_fp16.h>

#define BB   128
#define TT   1024
#define NIN  512
#define HH   1024
#define NOUT 256
#define NG   4096
#define NCTA 128

#define WSTRIDE 1032                      // halves; 2064B rows (129 x 16B) LDSM conflict-free
#define WBYTES  (32 * WSTRIDE * 2)        // 66048
#define NCHUNK  16

#define SAY 72
#define SMEM_Y ((BB + NOUT) * SAY * 2)
#define XG_SMEM (2 * 128 * 72 * 2)

// ---------------- device scratch ----------------
__device__ __half  g_Wp [(size_t)NCTA * 32 * HH];        // recurrent W [cta][l=32][k=1024], k-PERMUTED
__device__ __half  g_WuT[(size_t)NG * NIN];              // input W^T [l][k]
__device__ __half  g_u16[(size_t)TT * BB * NIN];         // [t][b][n]
__device__ __half  g_histx[(size_t)(TT + 1) * BB * HH];  // h[0..TT], natural columns
__device__ __half  g_Wy [(size_t)NOUT * HH];             // W_hy^T [n][k]
__device__ float   g_X  [(size_t)TT * NG * BB];          // u-gate pre-acts (+bias)
__device__ unsigned g_flag[(TT + 1) * 16];               // per (t, col-group): 64 warp-arrivals

// W-side k permutation (involution on pairs within a 32-half block):
// storage pair q holds logical pair 4*(q&3) + (q>>2); h stays natural so a
// lane's contiguous uint4 of h matches the permuted-W B-fragments.
__device__ __forceinline__ int permk(int k) {
    int kp = (k >> 1) & 15;
    int tp = ((kp & 3) << 2) | (kp >> 2);
    return (k & ~31) | (tp << 1) | (k & 1);
}

// ---------------- ptx helpers ----------------
__device__ __forceinline__ unsigned smem_u32(const void* p) {
    unsigned a;
    asm("{ .reg .u64 t; cvta.to.shared.u64 t, %1; cvt.u32.u64 %0, t; }" : "=r"(a) : "l"(p));
    return a;
}
#define LDSM4(r0, r1, r2, r3, a) \
    asm volatile("ldmatrix.sync.aligned.m8n8.x4.shared.b16 {%0,%1,%2,%3}, [%4];" \
                 : "=r"(r0), "=r"(r1), "=r"(r2), "=r"(r3) : "r"((unsigned)(a)))

__device__ __forceinline__ void mma16816(float* c, unsigned a0, unsigned a1, unsigned a2, unsigned a3,
                                         unsigned b0, unsigned b1) {
    asm volatile(
        "mma.sync.aligned.m16n8k16.row.col.f32.f16.f16.f32 "
        "{%0,%1,%2,%3}, {%4,%5,%6,%7}, {%8,%9}, {%0,%1,%2,%3};"
        : "+f"(c[0]), "+f"(c[1]), "+f"(c[2]), "+f"(c[3])
        : "r"(a0), "r"(a1), "r"(a2), "r"(a3), "r"(b0), "r"(b1));
}
__device__ __forceinline__ float tanha(float x) {
    float r; asm("tanh.approx.f32 %0, %1;" : "=f"(r) : "f"(x)); return r;
}
__device__ __forceinline__ float siga(float x) { return 0.5f * tanha(0.5f * x) + 0.5f; }

__device__ __forceinline__ void wait_flag(const unsigned* p) {
    unsigned v;
    asm volatile("ld.acquire.gpu.global.u32 %0, [%1];" : "=r"(v) : "l"(p));
    if (v < 64u) {
        do {
            __nanosleep(32);
            asm volatile("ld.acquire.gpu.global.u32 %0, [%1];" : "=r"(v) : "l"(p));
        } while (v < 64u);
    }
}
__device__ __forceinline__ void release_flag(unsigned* p) {
    asm volatile("red.release.gpu.global.add.u32 [%0], %1;" :: "l"(p), "r"(1u) : "memory");
}

// ---------------- prep ----------------
__global__ void pack_wh_kernel(const float* __restrict__ Whf, const float* __restrict__ Whi,
                               const float* __restrict__ Who, const float* __restrict__ Whc)
{
    int idx = blockIdx.x * blockDim.x + threadIdx.x;
    if (idx >= NCTA * 32 * HH) return;
    int k = idx & (HH - 1);
    int l = (idx >> 10) & 31;
    int cta = idx >> 15;
    int g = (l >> 3) & 3;
    int j = cta * 8 + (l & 7);
    const float* W = (g == 0) ? Whf : (g == 1) ? Whi : (g == 2) ? Who : Whc;
    g_Wp[idx] = __float2half_rn(W[(size_t)permk(k) * HH + j]);   // ONLY W is k-permuted
}

__global__ void pack_wut_kernel(const float* __restrict__ Wuf, const float* __restrict__ Wui,
                                const float* __restrict__ Wuo, const float* __restrict__ Wuc)
{
    int idx = blockIdx.x * blockDim.x + threadIdx.x;
    if (idx >= NG * NIN) return;
    int k = idx & (NIN - 1);
    int l = idx >> 9;
    int g = (l >> 3) & 3;
    int j = (l >> 5) * 8 + (l & 7);
    const float* W = (g == 0) ? Wuf : (g == 1) ? Wui : (g == 2) ? Wuo : Wuc;
    g_WuT[idx] = __float2half_rn(W[(size_t)k * HH + j]);
}

__global__ void pack_u_kernel(const float* __restrict__ u)
{
    long long idx = (long long)blockIdx.x * blockDim.x + threadIdx.x;
    if (idx >= (long long)BB * TT * NIN) return;
    int n = (int)(idx & (NIN - 1));
    int t = (int)((idx >> 9) & (TT - 1));
    int b = (int)(idx >> 19);
    g_u16[((size_t)t * BB + b) * NIN + n] = __float2half_rn(u[idx]);
}

__global__ void pack_misc_kernel(const float* __restrict__ Why, const float* __restrict__ h0)
{
    int idx = blockIdx.x * blockDim.x + threadIdx.x;
    if (idx < NOUT * HH) {
        int n = idx / HH, k = idx % HH;
        g_Wy[idx] = __float2half_rn(Why[(size_t)k * NOUT + n]);
    }
    if (idx < BB * HH) {
        g_histx[idx] = __float2half_rn(h0[idx & (HH - 1)]);
    }
    if (idx < (TT + 1) * 16) {
        g_flag[idx] = (idx < 16) ? 64u : 0u;     // h[0] ready (64 warp-arrivals)
    }
}

// ---------------- X GEMM: X[t][l][b] = sum_k WuT[l][k]*u[t][b][k] + bias[l] ----------------
__global__ void __launch_bounds__(256, 2)
xgemm_kernel(const float* __restrict__ bf, const float* __restrict__ bi,
             const float* __restrict__ bo, const float* __restrict__ bc)
{
    extern __shared__ char sm[];
    __half* As = (__half*)sm;                 // [128 l][72]
    __half* Bs = (__half*)sm + 128 * 72;      // [128 b][72]
    const unsigned asb = smem_u32(As), bsb = smem_u32(Bs);

    const int tid = threadIdx.x, w = tid >> 5, lane = tid & 31;
    const int gq = lane >> 2, tg = lane & 3;
    const int bx = blockIdx.x, t = blockIdx.y;
    const int i8 = lane & 7, sel = lane >> 3;
    const unsigned aLane = ((w * 16 + (lane & 15)) * 144) + ((lane >> 4) * 16);
    const unsigned bRowOff = ((((sel >> 1) & 1) * 8 + i8) * 144) + ((sel & 1) * 16);

    float acc[16][4];
    #pragma unroll
    for (int nt = 0; nt < 16; ++nt)
        #pragma unroll
        for (int e = 0; e < 4; ++e) acc[nt][e] = 0.0f;

    for (int kc = 0; kc < NIN; kc += 64) {
        #pragma unroll
        for (int p = 0; p < 4; ++p) {
            int row = p * 32 + (tid >> 3), c8 = tid & 7;
            *(uint4*)(As + row * 72 + c8 * 8) =
                *(const uint4*)(g_WuT + (size_t)(bx * 128 + row) * NIN + kc + c8 * 8);
            *(uint4*)(Bs + row * 72 + c8 * 8) =
                *(const uint4*)(g_u16 + ((size_t)t * BB + row) * NIN + kc + c8 * 8);
        }
        __syncthreads();
        #pragma unroll
        for (int ks = 0; ks < 4; ++ks) {
            unsigned a0, a1, a2, a3;
            LDSM4(a0, a1, a2, a3, asb + aLane + ks * 32);
            #pragma unroll
            for (int p = 0; p < 8; ++p) {
                unsigned r0, r1, r2, r3;
                LDSM4(r0, r1, r2, r3, bsb + p * (16 * 144) + bRowOff + ks * 32);
                mma16816(acc[p * 2 + 0], a0, a1, a2, a3, r0, r1);
                mma16816(acc[p * 2 + 1], a0, a1, a2, a3, r2, r3);
            }
        }
        __syncthreads();
    }

    const float* bsel[4] = {bf, bi, bo, bc};
    #pragma unroll
    for (int rr = 0; rr < 2; ++rr) {
        int l = bx * 128 + w * 16 + gq + rr * 8;
        int g = (l >> 3) & 3;
        float bv = bsel[g][(l >> 5) * 8 + (l & 7)];
        float* orow = g_X + ((size_t)t * NG + l) * BB;
        #pragma unroll
        for (int nt = 0; nt < 16; ++nt) {
            float2 v = make_float2(acc[nt][rr * 2] + bv, acc[nt][rr * 2 + 1] + bv);
            *(float2*)(orow + nt * 8 + tg * 2) = v;
        }
    }
}

// ---------------- persistent recurrent kernel ----------------
// 8 MMA warps, FULLY decoupled: per-warp flag release (64 arrivals/group),
// no block-wide sync in the step loop. LDG.128 A-frags from natural h
// (W k-permuted); LDSM hoisted per chunk; lookahead-3 prefetch.
__global__ void __launch_bounds__(256, 1)
lstm_main(const float* __restrict__ h0)
{
    extern __shared__ char sm[];
    const unsigned smb = smem_u32(sm);
    const int tid = threadIdx.x, cta = blockIdx.x;
    const int w = tid >> 5, lane = tid & 31;
    const int gq = lane >> 2, tg = lane & 3;
    const int i8 = lane & 7, sel = lane >> 3;
    const unsigned bRowOff = ((((sel >> 1) & 1) * 8 + i8) * (WSTRIDE * 2)) + ((sel & 1) * 16);
    const int bb0 = w * 16 + gq;               // batch rows bb0, bb0+8
    const int j0  = cta * 8 + tg * 2;          // hidden cols (natural)
    const int c0  = cta >> 3;

    // resident recurrent W slice [32][1024] -> stride 1032 (k-permuted image)
    {
        const uint4* src = (const uint4*)(g_Wp + (size_t)cta * 32 * HH);
        for (int i = tid; i < 32 * 128; i += 256) {
            int r = i >> 7, c = i & 127;
            *(uint4*)((__half*)sm + r * WSTRIDE + c * 8) = src[(size_t)r * 128 + c];
        }
    }
    __syncthreads();

    float hold[2][2];
    hold[0][0] = hold[1][0] = h0[j0];
    hold[0][1] = hold[1][1] = h0[j0 + 1];

    for (int t = 0; t < TT; ++t) {
        const char* r0p = (const char*)(g_histx + (size_t)t * BB * HH + (size_t)bb0 * HH) + tg * 16;
        const char* r8p = r0p + 8 * (HH * 2);

        float acc[4][4];
        #pragma unroll
        for (int nt = 0; nt < 4; ++nt)
            #pragma unroll
            for (int e = 0; e < 4; ++e) acc[nt][e] = 0.0f;

        uint4 A[4][4];   // [buf][group*2 + row]: group = 32-k half of chunk, row in {gq, gq+8}
        #pragma unroll
        for (int pi = 0; pi < 3; ++pi) {
            int c = (c0 + pi) & 15;
            wait_flag(&g_flag[t * 16 + c]);
            const char* cb = r0p + c * 128;
            A[pi][0] = *(const uint4*)(cb);
            A[pi][1] = *(const uint4*)(r8p + c * 128);
            A[pi][2] = *(const uint4*)(cb + 64);
            A[pi][3] = *(const uint4*)(r8p + c * 128 + 64);
        }

        #pragma unroll
        for (int i = 0; i < NCHUNK; ++i) {
            if (i + 3 < NCHUNK) {
                int c = (c0 + i + 3) & 15;
                uint4* Ap = A[(i + 3) & 3];
                wait_flag(&g_flag[t * 16 + c]);
                const char* cb = r0p + c * 128;
                Ap[0] = *(const uint4*)(cb);
                Ap[1] = *(const uint4*)(r8p + c * 128);
                Ap[2] = *(const uint4*)(cb + 64);
                Ap[3] = *(const uint4*)(r8p + c * 128 + 64);
            }
            const uint4* Ac = A[i & 3];
            const unsigned kb = smb + bRowOff + (unsigned)(((c0 + i) & 15) * 128);

            unsigned br[4][4], bs[4][4];
            #pragma unroll
            for (int ks = 0; ks < 4; ++ks)
                LDSM4(br[ks][0], br[ks][1], br[ks][2], br[ks][3], kb + ks * 32);
            #pragma unroll
            for (int ks = 0; ks < 4; ++ks)
                LDSM4(bs[ks][0], bs[ks][1], bs[ks][2], bs[ks][3],
                      kb + 16 * (WSTRIDE * 2) + ks * 32);

            #pragma unroll
            for (int ks = 0; ks < 4; ++ks) {
                const uint4 q0 = Ac[(ks >> 1) * 2], q8 = Ac[(ks >> 1) * 2 + 1];
                unsigned a0, a1, a2, a3;
                if ((ks & 1) == 0) { a0 = q0.x; a1 = q8.x; a2 = q0.y; a3 = q8.y; }
                else               { a0 = q0.z; a1 = q8.z; a2 = q0.w; a3 = q8.w; }
                mma16816(acc[0], a0, a1, a2, a3, br[ks][0], br[ks][1]);
                mma16816(acc[1], a0, a1, a2, a3, br[ks][2], br[ks][3]);
                mma16816(acc[2], a0, a1, a2, a3, bs[ks][0], bs[ks][1]);
                mma16816(acc[3], a0, a1, a2, a3, bs[ks][2], bs[ks][3]);
            }
        }

        // X loads (issued while last MMA chains drain)
        float xr[16];
        #pragma unroll
        for (int g = 0; g < 4; ++g)
            #pragma unroll
            for (int cc = 0; cc < 2; ++cc)
                #pragma unroll
                for (int rr = 0; rr < 2; ++rr)
                    xr[g * 4 + cc * 2 + rr] =
                        g_X[((size_t)t * NG + cta * 32 + g * 8 + tg * 2 + cc) * BB + bb0 + rr * 8];

        // epilogue: gates (n-tiles are the 4 gates), register h_old, natural store
        __half* hw = g_histx + (size_t)(t + 1) * BB * HH;
        #pragma unroll
        for (int rr = 0; rr < 2; ++rr) {
            float hn[2];
            #pragma unroll
            for (int cc = 0; cc < 2; ++cc) {
                int e = rr * 2 + cc;
                float f  = siga (acc[0][e] + xr[0 * 4 + cc * 2 + rr]);
                float ii = siga (acc[1][e] + xr[1 * 4 + cc * 2 + rr]);
                float o  = siga (acc[2][e] + xr[2 * 4 + cc * 2 + rr]);
                float ct = tanha(acc[3][e] + xr[3 * 4 + cc * 2 + rr]);
                float cn = f * hold[rr][cc] + ii * ct;     // faithful: uses h, not c
                hn[cc] = o * tanha(cn);
                hold[rr][cc] = hn[cc];
            }
            *(__half2*)(hw + (size_t)(bb0 + rr * 8) * HH + j0) = __floats2half2_rn(hn[0], hn[1]);
        }

        // per-warp release: no block-wide sync; warps drift freely across steps
        __syncwarp();
        if (lane == 0) release_flag(&g_flag[(t + 1) * 16 + (cta >> 3)]);
    }
}

// ---------------- output pass: y = softmax(hist @ Wy + by) ----------------
__global__ void __launch_bounds__(256, 1)
y_kernel(const float* __restrict__ by, float* __restrict__ out)
{
    extern __shared__ char sm[];
    __half* As = (__half*)sm;
    __half* Bs = (__half*)sm + BB * SAY;

    const int tid = threadIdx.x, w = tid >> 5, lane = tid & 31;
    const int gq = lane >> 2, tg = lane & 3;
    const int t = blockIdx.x;
    const size_t rowbase = (size_t)(t + 1) * BB;            // y_t from h[t+1]
    const int R1 = w * 16 + gq;

    float acc[32][4];
    #pragma unroll
    for (int nt = 0; nt < 32; ++nt)
        #pragma unroll
        for (int e = 0; e < 4; ++e) acc[nt][e] = 0.0f;

    for (int kc = 0; kc < HH; kc += 64) {
        #pragma unroll
        for (int p = 0; p < 4; ++p) {
            int row = p * 32 + (tid >> 3), c8 = tid & 7;
            *(uint4*)(As + row * SAY + c8 * 8) =
                *(const uint4*)(g_histx + (rowbase + row) * HH + kc + c8 * 8);
        }
        #pragma unroll
        for (int p = 0; p < 8; ++p) {
            int row = p * 32 + (tid >> 3), c8 = tid & 7;
            *(uint4*)(Bs + row * SAY + c8 * 8) =
                *(const uint4*)(g_Wy + (size_t)row * HH + kc + c8 * 8);
        }
        __syncthreads();
        #pragma unroll
        for (int ks = 0; ks < 64; ks += 16) {
            const __half* Ap = As + R1 * SAY + ks + tg * 2;
            unsigned a0 = *(const unsigned*)(Ap);
            unsigned a1 = *(const unsigned*)(Ap + 8 * SAY);
            unsigned a2 = *(const unsigned*)(Ap + 8);
            unsigned a3 = *(const unsigned*)(Ap + 8 * SAY + 8);
            #pragma unroll
            for (int nt = 0; nt < 32; ++nt) {
                const __half* Bp = Bs + (nt * 8 + gq) * SAY + ks + tg * 2;
                mma16816(acc[nt], a0, a1, a2, a3,
                         *(const unsigned*)(Bp), *(const unsigned*)(Bp + 8));
            }
        }
        __syncthreads();
    }

    #pragma unroll
    for (int rr = 0; rr < 2; ++rr) {
        float m = -1e30f;
        #pragma unroll
        for (int nt = 0; nt < 32; ++nt)
            #pragma unroll
            for (int c = 0; c < 2; ++c) {
                float v = acc[nt][rr * 2 + c] + __ldg(&by[nt * 8 + tg * 2 + c]);
                acc[nt][rr * 2 + c] = v;
                m = fmaxf(m, v);
            }
        m = fmaxf(m, __shfl_xor_sync(0xffffffffu, m, 1));
        m = fmaxf(m, __shfl_xor_sync(0xffffffffu, m, 2));
        float s = 0.0f;
        #pragma unroll
        for (int nt = 0; nt < 32; ++nt)
            #pragma unroll
            for (int c = 0; c < 2; ++c) {
                float e = __expf(acc[nt][rr * 2 + c] - m);
                acc[nt][rr * 2 + c] = e;
                s += e;
            }
        s += __shfl_xor_sync(0xffffffffu, s, 1);
        s += __shfl_xor_sync(0xffffffffu, s, 2);
        float inv = 1.0f / s;
        int b = R1 + rr * 8;
        float* orow = out + ((size_t)b * TT + t) * NOUT;
        #pragma unroll
        for (int nt = 0; nt < 32; ++nt) {
            float2 pr = make_float2(acc[nt][rr * 2] * inv, acc[nt][rr * 2 + 1] * inv);
            *(float2*)(orow + nt * 8 + tg * 2) = pr;
        }
    }
}

// ---------------- launcher ----------------
extern "C" void kernel_launch(void* const* d_in, const int* in_sizes, int n_in,
                              void* d_out, int out_size)
{
    const float* u   = (const float*)d_in[0];
    const float* Wuf = (const float*)d_in[1];
    const float* Wui = (const float*)d_in[2];
    const float* Wuo = (const float*)d_in[3];
    const float* Wuc = (const float*)d_in[4];
    const float* Whf = (const float*)d_in[5];
    const float* Whi = (const float*)d_in[6];
    const float* Who = (const float*)d_in[7];
    const float* Whc = (const float*)d_in[8];
    const float* Why = (const float*)d_in[9];
    const float* bf  = (const float*)d_in[10];
    const float* bi  = (const float*)d_in[11];
    const float* bo  = (const float*)d_in[12];
    const float* bc  = (const float*)d_in[13];
    const float* by  = (const float*)d_in[14];
    const float* h0  = (const float*)d_in[15];
    float* out = (float*)d_out;

    cudaFuncSetAttribute(lstm_main, cudaFuncAttributeMaxDynamicSharedMemorySize, WBYTES);
    cudaFuncSetAttribute(y_kernel,  cudaFuncAttributeMaxDynamicSharedMemorySize, SMEM_Y);

    pack_wh_kernel<<<(NCTA * 32 * HH) / 256, 256>>>(Whf, Whi, Who, Whc);
    pack_wut_kernel<<<(NG * NIN) / 256, 256>>>(Wuf, Wui, Wuo, Wuc);
    pack_u_kernel<<<(BB * TT * NIN) / 256, 256>>>(u);
    pack_misc_kernel<<<1024, 256>>>(Why, h0);
    xgemm_kernel<<<dim3(NG / 128, TT), 256, XG_SMEM>>>(bf, bi, bo, bc);
    lstm_main<<<NCTA, 256, WBYTES>>>(h0);
    y_kernel<<<TT, 256, SMEM_Y>>>(by, out);
}

// round 14
// speedup vs baseline: 1.0578x; 1.0578x over previous
#include <cuda_runtime.h>
#include <cuda_fp16.h>

#define BB   128
#define TT   1024
#define NIN  512
#define HH   1024
#define NOUT 256
#define NG   4096
#define NCTA 128

#define WSTRIDE 1032                      // halves; 2064B rows (129 x 16B) LDSM conflict-free
#define WBYTES  (32 * WSTRIDE * 2)        // 66048
#define NCHUNK  16
#define SMEM_MAIN (WBYTES + 16)           // + arrival counter

#define SAY 72
#define SMEM_Y ((BB + NOUT) * SAY * 2)
#define XG_SMEM (2 * 128 * 72 * 2)

// ---------------- device scratch ----------------
__device__ __half  g_Wp [(size_t)NCTA * 32 * HH];        // recurrent W [cta][l=32][k=1024], k-PERMUTED
__device__ __half  g_WuT[(size_t)NG * NIN];              // input W^T [l][k]
__device__ __half  g_u16[(size_t)TT * BB * NIN];         // [t][b][n]
__device__ __half  g_histx[(size_t)(TT + 1) * BB * HH];  // h[0..TT], natural columns
__device__ __half  g_Wy [(size_t)NOUT * HH];             // W_hy^T [n][k]
__device__ float   g_X  [(size_t)TT * NG * BB];          // u-gate pre-acts (+bias)
__device__ unsigned g_flag[(TT + 1) * 16];               // per (t, col-group): 8 CTA arrivals

// W-side k permutation (involution on pairs within a 32-half block):
// storage pair q holds logical pair 4*(q&3) + (q>>2); h stays natural so a
// lane's contiguous uint4 of h matches the permuted-W B-fragments.
__device__ __forceinline__ int permk(int k) {
    int kp = (k >> 1) & 15;
    int tp = ((kp & 3) << 2) | (kp >> 2);
    return (k & ~31) | (tp << 1) | (k & 1);
}

// ---------------- ptx helpers ----------------
__device__ __forceinline__ unsigned smem_u32(const void* p) {
    unsigned a;
    asm("{ .reg .u64 t; cvta.to.shared.u64 t, %1; cvt.u32.u64 %0, t; }" : "=r"(a) : "l"(p));
    return a;
}
#define LDSM4(r0, r1, r2, r3, a) \
    asm volatile("ldmatrix.sync.aligned.m8n8.x4.shared.b16 {%0,%1,%2,%3}, [%4];" \
                 : "=r"(r0), "=r"(r1), "=r"(r2), "=r"(r3) : "r"((unsigned)(a)))

__device__ __forceinline__ void mma16816(float* c, unsigned a0, unsigned a1, unsigned a2, unsigned a3,
                                         unsigned b0, unsigned b1) {
    asm volatile(
        "mma.sync.aligned.m16n8k16.row.col.f32.f16.f16.f32 "
        "{%0,%1,%2,%3}, {%4,%5,%6,%7}, {%8,%9}, {%0,%1,%2,%3};"
        : "+f"(c[0]), "+f"(c[1]), "+f"(c[2]), "+f"(c[3])
        : "r"(a0), "r"(a1), "r"(a2), "r"(a3), "r"(b0), "r"(b1));
}
__device__ __forceinline__ float tanha(float x) {
    float r; asm("tanh.approx.f32 %0, %1;" : "=f"(r) : "f"(x)); return r;
}
__device__ __forceinline__ float siga(float x) { return 0.5f * tanha(0.5f * x) + 0.5f; }

__device__ __forceinline__ void wait_flag(const unsigned* p) {
    unsigned v;
    asm volatile("ld.acquire.gpu.global.u32 %0, [%1];" : "=r"(v) : "l"(p));
    if (v < 8u) {
        do {
            __nanosleep(32);
            asm volatile("ld.acquire.gpu.global.u32 %0, [%1];" : "=r"(v) : "l"(p));
        } while (v < 8u);
    }
}
__device__ __forceinline__ void release_flag(unsigned* p) {
    asm volatile("red.release.gpu.global.add.u32 [%0], %1;" :: "l"(p), "r"(1u) : "memory");
}
// cta-scoped acq_rel arrival on a shared-memory counter; returns old value.
__device__ __forceinline__ unsigned smem_arrive(unsigned addr) {
    unsigned old;
    asm volatile("atom.acq_rel.cta.shared::cta.add.u32 %0, [%1], %2;"
                 : "=r"(old) : "r"(addr), "r"(1u) : "memory");
    return old;
}

// ---------------- prep (merged: lstm_main must be the 4th kernel node) ----------------
__global__ void pack_A(const float* __restrict__ Whf, const float* __restrict__ Whi,
                       const float* __restrict__ Who, const float* __restrict__ Whc,
                       const float* __restrict__ Wuf, const float* __restrict__ Wui,
                       const float* __restrict__ Wuo, const float* __restrict__ Wuc)
{
    int idx = blockIdx.x * blockDim.x + threadIdx.x;
    if (idx < NCTA * 32 * HH) {                     // recurrent W, k-permuted
        int k = idx & (HH - 1);
        int l = (idx >> 10) & 31;
        int cta = idx >> 15;
        int g = (l >> 3) & 3;
        int j = cta * 8 + (l & 7);
        const float* W = (g == 0) ? Whf : (g == 1) ? Whi : (g == 2) ? Who : Whc;
        g_Wp[idx] = __float2half_rn(W[(size_t)permk(k) * HH + j]);
    }
    if (idx < NG * NIN) {                           // input W^T, natural
        int k = idx & (NIN - 1);
        int l = idx >> 9;
        int g = (l >> 3) & 3;
        int j = (l >> 5) * 8 + (l & 7);
        const float* W = (g == 0) ? Wuf : (g == 1) ? Wui : (g == 2) ? Wuo : Wuc;
        g_WuT[idx] = __float2half_rn(W[(size_t)k * HH + j]);
    }
}

__global__ void pack_B(const float* __restrict__ u, const float* __restrict__ Why,
                       const float* __restrict__ h0)
{
    long long idx = (long long)blockIdx.x * blockDim.x + threadIdx.x;
    if (idx < (long long)BB * TT * NIN) {
        int n = (int)(idx & (NIN - 1));
        int t = (int)((idx >> 9) & (TT - 1));
        int b = (int)(idx >> 19);
        g_u16[((size_t)t * BB + b) * NIN + n] = __float2half_rn(u[idx]);
    }
    if (idx < NOUT * HH) {
        int n = (int)idx / HH, k = (int)idx % HH;
        g_Wy[idx] = __float2half_rn(Why[(size_t)k * NOUT + n]);
    }
    if (idx < BB * HH) {
        g_histx[idx] = __float2half_rn(h0[idx & (HH - 1)]);
    }
    if (idx < (TT + 1) * 16) {
        g_flag[idx] = (idx < 16) ? 8u : 0u;
    }
}

// ---------------- X GEMM: X[t][l][b] = sum_k WuT[l][k]*u[t][b][k] + bias[l] ----------------
__global__ void __launch_bounds__(256, 2)
xgemm_kernel(const float* __restrict__ bf, const float* __restrict__ bi,
             const float* __restrict__ bo, const float* __restrict__ bc)
{
    extern __shared__ char sm[];
    __half* As = (__half*)sm;                 // [128 l][72]
    __half* Bs = (__half*)sm + 128 * 72;      // [128 b][72]
    const unsigned asb = smem_u32(As), bsb = smem_u32(Bs);

    const int tid = threadIdx.x, w = tid >> 5, lane = tid & 31;
    const int gq = lane >> 2, tg = lane & 3;
    const int bx = blockIdx.x, t = blockIdx.y;
    const int i8 = lane & 7, sel = lane >> 3;
    const unsigned aLane = ((w * 16 + (lane & 15)) * 144) + ((lane >> 4) * 16);
    const unsigned bRowOff = ((((sel >> 1) & 1) * 8 + i8) * 144) + ((sel & 1) * 16);

    float acc[16][4];
    #pragma unroll
    for (int nt = 0; nt < 16; ++nt)
        #pragma unroll
        for (int e = 0; e < 4; ++e) acc[nt][e] = 0.0f;

    for (int kc = 0; kc < NIN; kc += 64) {
        #pragma unroll
        for (int p = 0; p < 4; ++p) {
            int row = p * 32 + (tid >> 3), c8 = tid & 7;
            *(uint4*)(As + row * 72 + c8 * 8) =
                *(const uint4*)(g_WuT + (size_t)(bx * 128 + row) * NIN + kc + c8 * 8);
            *(uint4*)(Bs + row * 72 + c8 * 8) =
                *(const uint4*)(g_u16 + ((size_t)t * BB + row) * NIN + kc + c8 * 8);
        }
        __syncthreads();
        #pragma unroll
        for (int ks = 0; ks < 4; ++ks) {
            unsigned a0, a1, a2, a3;
            LDSM4(a0, a1, a2, a3, asb + aLane + ks * 32);
            #pragma unroll
            for (int p = 0; p < 8; ++p) {
                unsigned r0, r1, r2, r3;
                LDSM4(r0, r1, r2, r3, bsb + p * (16 * 144) + bRowOff + ks * 32);
                mma16816(acc[p * 2 + 0], a0, a1, a2, a3, r0, r1);
                mma16816(acc[p * 2 + 1], a0, a1, a2, a3, r2, r3);
            }
        }
        __syncthreads();
    }

    const float* bsel[4] = {bf, bi, bo, bc};
    #pragma unroll
    for (int rr = 0; rr < 2; ++rr) {
        int l = bx * 128 + w * 16 + gq + rr * 8;
        int g = (l >> 3) & 3;
        float bv = bsel[g][(l >> 5) * 8 + (l & 7)];
        float* orow = g_X + ((size_t)t * NG + l) * BB;
        #pragma unroll
        for (int nt = 0; nt < 16; ++nt) {
            float2 v = make_float2(acc[nt][rr * 2] + bv, acc[nt][rr * 2 + 1] + bv);
            *(float2*)(orow + nt * 8 + tg * 2) = v;
        }
    }
}

// ---------------- persistent recurrent kernel ----------------
// 8 MMA warps. LDG.128 A-frags from natural h (W k-permuted); LDSM hoisted per
// chunk; lookahead-2. No __syncthreads in the step loop: warps arrive on a
// SMEM monotonic counter; the 8th arriver issues the single global release.
// X loads hoisted before the MMA loop (latency hidden under 16 chunks).
__global__ void __launch_bounds__(256, 1)
lstm_main(const float* __restrict__ h0)
{
    extern __shared__ char sm[];
    const unsigned smb = smem_u32(sm);
    const unsigned cntAddr = smb + WBYTES;
    const int tid = threadIdx.x, cta = blockIdx.x;
    const int w = tid >> 5, lane = tid & 31;
    const int gq = lane >> 2, tg = lane & 3;
    const int i8 = lane & 7, sel = lane >> 3;
    const unsigned bRowOff = ((((sel >> 1) & 1) * 8 + i8) * (WSTRIDE * 2)) + ((sel & 1) * 16);
    const int bb0 = w * 16 + gq;               // batch rows bb0, bb0+8
    const int j0  = cta * 8 + tg * 2;          // hidden cols (natural)
    const int c0  = cta >> 3;

    // resident recurrent W slice [32][1024] -> stride 1032 (k-permuted image)
    {
        const uint4* src = (const uint4*)(g_Wp + (size_t)cta * 32 * HH);
        for (int i = tid; i < 32 * 128; i += 256) {
            int r = i >> 7, c = i & 127;
            *(uint4*)((__half*)sm + r * WSTRIDE + c * 8) = src[(size_t)r * 128 + c];
        }
    }
    if (tid == 0) *(unsigned*)(sm + WBYTES) = 0u;
    __syncthreads();

    float hold[2][2];
    hold[0][0] = hold[1][0] = h0[j0];
    hold[0][1] = hold[1][1] = h0[j0 + 1];

    for (int t = 0; t < TT; ++t) {
        const char* r0p = (const char*)(g_histx + (size_t)t * BB * HH + (size_t)bb0 * HH) + tg * 16;
        const char* r8p = r0p + 8 * (HH * 2);

        float acc[4][4];
        #pragma unroll
        for (int nt = 0; nt < 4; ++nt)
            #pragma unroll
            for (int e = 0; e < 4; ++e) acc[nt][e] = 0.0f;

        uint4 A[3][4];   // [buf][group*2 + row]: group = 32-k half of chunk, row in {gq, gq+8}
        #pragma unroll
        for (int pi = 0; pi < 2; ++pi) {
            int c = (c0 + pi) & 15;
            wait_flag(&g_flag[t * 16 + c]);
            const char* cb = r0p + c * 128;
            A[pi][0] = *(const uint4*)(cb);
            A[pi][1] = *(const uint4*)(r8p + c * 128);
            A[pi][2] = *(const uint4*)(cb + 64);
            A[pi][3] = *(const uint4*)(r8p + c * 128 + 64);
        }

        // X preloads issued NOW, consumed after 16 chunks of MMA (latency hidden)
        float xr[16];
        #pragma unroll
        for (int g = 0; g < 4; ++g)
            #pragma unroll
            for (int cc = 0; cc < 2; ++cc)
                #pragma unroll
                for (int rr = 0; rr < 2; ++rr)
                    xr[g * 4 + cc * 2 + rr] =
                        g_X[((size_t)t * NG + cta * 32 + g * 8 + tg * 2 + cc) * BB + bb0 + rr * 8];

        #pragma unroll
        for (int i = 0; i < NCHUNK; ++i) {
            if (i + 2 < NCHUNK) {
                int c = (c0 + i + 2) & 15;
                uint4* Ap = A[(i + 2) % 3];
                wait_flag(&g_flag[t * 16 + c]);
                const char* cb = r0p + c * 128;
                Ap[0] = *(const uint4*)(cb);
                Ap[1] = *(const uint4*)(r8p + c * 128);
                Ap[2] = *(const uint4*)(cb + 64);
                Ap[3] = *(const uint4*)(r8p + c * 128 + 64);
            }
            const uint4* Ac = A[i % 3];
            const unsigned kb = smb + bRowOff + (unsigned)(((c0 + i) & 15) * 128);

            unsigned br[4][4], bs[4][4];
            #pragma unroll
            for (int ks = 0; ks < 4; ++ks)
                LDSM4(br[ks][0], br[ks][1], br[ks][2], br[ks][3], kb + ks * 32);
            #pragma unroll
            for (int ks = 0; ks < 4; ++ks)
                LDSM4(bs[ks][0], bs[ks][1], bs[ks][2], bs[ks][3],
                      kb + 16 * (WSTRIDE * 2) + ks * 32);

            #pragma unroll
            for (int ks = 0; ks < 4; ++ks) {
                const uint4 q0 = Ac[(ks >> 1) * 2], q8 = Ac[(ks >> 1) * 2 + 1];
                unsigned a0, a1, a2, a3;
                if ((ks & 1) == 0) { a0 = q0.x; a1 = q8.x; a2 = q0.y; a3 = q8.y; }
                else               { a0 = q0.z; a1 = q8.z; a2 = q0.w; a3 = q8.w; }
                mma16816(acc[0], a0, a1, a2, a3, br[ks][0], br[ks][1]);
                mma16816(acc[1], a0, a1, a2, a3, br[ks][2], br[ks][3]);
                mma16816(acc[2], a0, a1, a2, a3, bs[ks][0], bs[ks][1]);
                mma16816(acc[3], a0, a1, a2, a3, bs[ks][2], bs[ks][3]);
            }
        }

        // epilogue: gates (n-tiles are the 4 gates), register h_old, natural store
        __half* hw = g_histx + (size_t)(t + 1) * BB * HH;
        #pragma unroll
        for (int rr = 0; rr < 2; ++rr) {
            float hn[2];
            #pragma unroll
            for (int cc = 0; cc < 2; ++cc) {
                int e = rr * 2 + cc;
                float f  = siga (acc[0][e] + xr[0 * 4 + cc * 2 + rr]);
                float ii = siga (acc[1][e] + xr[1 * 4 + cc * 2 + rr]);
                float o  = siga (acc[2][e] + xr[2 * 4 + cc * 2 + rr]);
                float ct = tanha(acc[3][e] + xr[3 * 4 + cc * 2 + rr]);
                float cn = f * hold[rr][cc] + ii * ct;     // faithful: uses h, not c
                hn[cc] = o * tanha(cn);
                hold[rr][cc] = hn[cc];
            }
            *(__half2*)(hw + (size_t)(bb0 + rr * 8) * HH + j0) = __floats2half2_rn(hn[0], hn[1]);
        }

        // decoupled arrival: 8th warp of this CTA fires the single global release.
        __syncwarp();
        if (lane == 0) {
            unsigned old = smem_arrive(cntAddr);
            if (old == (unsigned)(t * 8 + 7))
                release_flag(&g_flag[(t + 1) * 16 + (cta >> 3)]);
        }
    }
}

// ---------------- output pass: y = softmax(hist @ Wy + by) ----------------
__global__ void __launch_bounds__(256, 1)
y_kernel(const float* __restrict__ by, float* __restrict__ out)
{
    extern __shared__ char sm[];
    __half* As = (__half*)sm;
    __half* Bs = (__half*)sm + BB * SAY;

    const int tid = threadIdx.x, w = tid >> 5, lane = tid & 31;
    const int gq = lane >> 2, tg = lane & 3;
    const int t = blockIdx.x;
    const size_t rowbase = (size_t)(t + 1) * BB;            // y_t from h[t+1]
    const int R1 = w * 16 + gq;

    float acc[32][4];
    #pragma unroll
    for (int nt = 0; nt < 32; ++nt)
        #pragma unroll
        for (int e = 0; e < 4; ++e) acc[nt][e] = 0.0f;

    for (int kc = 0; kc < HH; kc += 64) {
        #pragma unroll
        for (int p = 0; p < 4; ++p) {
            int row = p * 32 + (tid >> 3), c8 = tid & 7;
            *(uint4*)(As + row * SAY + c8 * 8) =
                *(const uint4*)(g_histx + (rowbase + row) * HH + kc + c8 * 8);
        }
        #pragma unroll
        for (int p = 0; p < 8; ++p) {
            int row = p * 32 + (tid >> 3), c8 = tid & 7;
            *(uint4*)(Bs + row * SAY + c8 * 8) =
                *(const uint4*)(g_Wy + (size_t)row * HH + kc + c8 * 8);
        }
        __syncthreads();
        #pragma unroll
        for (int ks = 0; ks < 64; ks += 16) {
            const __half* Ap = As + R1 * SAY + ks + tg * 2;
            unsigned a0 = *(const unsigned*)(Ap);
            unsigned a1 = *(const unsigned*)(Ap + 8 * SAY);
            unsigned a2 = *(const unsigned*)(Ap + 8);
            unsigned a3 = *(const unsigned*)(Ap + 8 * SAY + 8);
            #pragma unroll
            for (int nt = 0; nt < 32; ++nt) {
                const __half* Bp = Bs + (nt * 8 + gq) * SAY + ks + tg * 2;
                mma16816(acc[nt], a0, a1, a2, a3,
                         *(const unsigned*)(Bp), *(const unsigned*)(Bp + 8));
            }
        }
        __syncthreads();
    }

    #pragma unroll
    for (int rr = 0; rr < 2; ++rr) {
        float m = -1e30f;
        #pragma unroll
        for (int nt = 0; nt < 32; ++nt)
            #pragma unroll
            for (int c = 0; c < 2; ++c) {
                float v = acc[nt][rr * 2 + c] + __ldg(&by[nt * 8 + tg * 2 + c]);
                acc[nt][rr * 2 + c] = v;
                m = fmaxf(m, v);
            }
        m = fmaxf(m, __shfl_xor_sync(0xffffffffu, m, 1));
        m = fmaxf(m, __shfl_xor_sync(0xffffffffu, m, 2));
        float s = 0.0f;
        #pragma unroll
        for (int nt = 0; nt < 32; ++nt)
            #pragma unroll
            for (int c = 0; c < 2; ++c) {
                float e = __expf(acc[nt][rr * 2 + c] - m);
                acc[nt][rr * 2 + c] = e;
                s += e;
            }
        s += __shfl_xor_sync(0xffffffffu, s, 1);
        s += __shfl_xor_sync(0xffffffffu, s, 2);
        float inv = 1.0f / s;
        int b = R1 + rr * 8;
        float* orow = out + ((size_t)b * TT + t) * NOUT;
        #pragma unroll
        for (int nt = 0; nt < 32; ++nt) {
            float2 pr = make_float2(acc[nt][rr * 2] * inv, acc[nt][rr * 2 + 1] * inv);
            *(float2*)(orow + nt * 8 + tg * 2) = pr;
        }
    }
}

// ---------------- launcher ----------------
extern "C" void kernel_launch(void* const* d_in, const int* in_sizes, int n_in,
                              void* d_out, int out_size)
{
    const float* u   = (const float*)d_in[0];
    const float* Wuf = (const float*)d_in[1];
    const float* Wui = (const float*)d_in[2];
    const float* Wuo = (const float*)d_in[3];
    const float* Wuc = (const float*)d_in[4];
    const float* Whf = (const float*)d_in[5];
    const float* Whi = (const float*)d_in[6];
    const float* Who = (const float*)d_in[7];
    const float* Whc = (const float*)d_in[8];
    const float* Why = (const float*)d_in[9];
    const float* bf  = (const float*)d_in[10];
    const float* bi  = (const float*)d_in[11];
    const float* bo  = (const float*)d_in[12];
    const float* bc  = (const float*)d_in[13];
    const float* by  = (const float*)d_in[14];
    const float* h0  = (const float*)d_in[15];
    float* out = (float*)d_out;

    cudaFuncSetAttribute(lstm_main, cudaFuncAttributeMaxDynamicSharedMemorySize, SMEM_MAIN);
    cudaFuncSetAttribute(y_kernel,  cudaFuncAttributeMaxDynamicSharedMemorySize, SMEM_Y);

    // 5 kernel nodes; lstm_main is the 4th (the node ncu's -s/-c window captures)
    pack_A<<<(NCTA * 32 * HH) / 256, 256>>>(Whf, Whi, Who, Whc, Wuf, Wui, Wuo, Wuc);
    pack_B<<<(int)(((long long)BB * TT * NIN) / 256), 256>>>(u, Why, h0);
    xgemm_kernel<<<dim3(NG / 128, TT), 256, XG_SMEM>>>(bf, bi, bo, bc);
    lstm_main<<<NCTA, 256, SMEM_MAIN>>>(h0);
    y_kernel<<<TT, 256, SMEM_Y>>>(by, out);
}

// round 15
// speedup vs baseline: 1.0802x; 1.0212x over previous
#include <cuda_runtime.h>
#include <cuda_fp16.h>

#define BB   128
#define TT   1024
#define NIN  512
#define HH   1024
#define NOUT 256
#define NG   4096
#define NCTA 128

#define WSTRIDE 1032                      // halves; 2064B rows (129 x 16B) LDSM conflict-free
#define WBYTES  (32 * WSTRIDE * 2)        // 66048
#define NCHUNK  16
#define SMEM_MAIN (WBYTES + 16)           // + arrival counter

#define SAY 72
#define SMEM_Y ((BB + NOUT) * SAY * 2)
#define XG_SMEM (2 * 128 * 72 * 2)

// ---------------- device scratch ----------------
__device__ __half  g_Wp [(size_t)NCTA * 32 * HH];        // recurrent W [cta][l=32][k=1024], k-PERMUTED
__device__ __half  g_WuT[(size_t)NG * NIN];              // input W^T [l][k]
__device__ __half  g_u16[(size_t)TT * BB * NIN];         // [t][b][n]
__device__ __half  g_histx[(size_t)(TT + 1) * BB * HH];  // h[0..TT], natural columns
__device__ __half  g_Wy [(size_t)NOUT * HH];             // W_hy^T [n][k]
__device__ float   g_X  [(size_t)TT * NG * BB];          // u-gate pre-acts (+bias)
__device__ unsigned g_flag[(TT + 1) * 16];               // per (t, col-group): 8 CTA arrivals

// W-side k permutation (involution on pairs within a 32-half block):
// storage pair q holds logical pair 4*(q&3) + (q>>2); h stays natural so a
// lane's contiguous uint4 of h matches the permuted-W B-fragments.
__device__ __forceinline__ int permk(int k) {
    int kp = (k >> 1) & 15;
    int tp = ((kp & 3) << 2) | (kp >> 2);
    return (k & ~31) | (tp << 1) | (k & 1);
}

// ---------------- ptx helpers ----------------
__device__ __forceinline__ unsigned smem_u32(const void* p) {
    unsigned a;
    asm("{ .reg .u64 t; cvta.to.shared.u64 t, %1; cvt.u32.u64 %0, t; }" : "=r"(a) : "l"(p));
    return a;
}
#define LDSM4(r0, r1, r2, r3, a) \
    asm volatile("ldmatrix.sync.aligned.m8n8.x4.shared.b16 {%0,%1,%2,%3}, [%4];" \
                 : "=r"(r0), "=r"(r1), "=r"(r2), "=r"(r3) : "r"((unsigned)(a)))

__device__ __forceinline__ void mma16816(float* c, unsigned a0, unsigned a1, unsigned a2, unsigned a3,
                                         unsigned b0, unsigned b1) {
    asm volatile(
        "mma.sync.aligned.m16n8k16.row.col.f32.f16.f16.f32 "
        "{%0,%1,%2,%3}, {%4,%5,%6,%7}, {%8,%9}, {%0,%1,%2,%3};"
        : "+f"(c[0]), "+f"(c[1]), "+f"(c[2]), "+f"(c[3])
        : "r"(a0), "r"(a1), "r"(a2), "r"(a3), "r"(b0), "r"(b1));
}
__device__ __forceinline__ float tanha(float x) {
    float r; asm("tanh.approx.f32 %0, %1;" : "=f"(r) : "f"(x)); return r;
}
__device__ __forceinline__ float siga(float x) { return 0.5f * tanha(0.5f * x) + 0.5f; }

__device__ __forceinline__ unsigned flag_ld(const unsigned* p) {
    unsigned v;
    asm volatile("ld.acquire.gpu.global.u32 %0, [%1];" : "=r"(v) : "l"(p) : "memory");
    return v;
}
__device__ __forceinline__ void wait_flag(const unsigned* p) {
    unsigned v;
    asm volatile("ld.acquire.gpu.global.u32 %0, [%1];" : "=r"(v) : "l"(p));
    if (v < 8u) {
        do {
            __nanosleep(32);
            asm volatile("ld.acquire.gpu.global.u32 %0, [%1];" : "=r"(v) : "l"(p));
        } while (v < 8u);
    }
}
__device__ __forceinline__ void release_flag(unsigned* p) {
    asm volatile("red.release.gpu.global.add.u32 [%0], %1;" :: "l"(p), "r"(1u) : "memory");
}
// cta-scoped acq_rel arrival on a shared-memory counter; returns old value.
__device__ __forceinline__ unsigned smem_arrive(unsigned addr) {
    unsigned old;
    asm volatile("atom.acq_rel.cta.shared::cta.add.u32 %0, [%1], %2;"
                 : "=r"(old) : "r"(addr), "r"(1u) : "memory");
    return old;
}

// ---------------- prep (merged: lstm_main stays the 4th kernel node) ----------------
__global__ void pack_A(const float* __restrict__ Whf, const float* __restrict__ Whi,
                       const float* __restrict__ Who, const float* __restrict__ Whc,
                       const float* __restrict__ Wuf, const float* __restrict__ Wui,
                       const float* __restrict__ Wuo, const float* __restrict__ Wuc)
{
    int idx = blockIdx.x * blockDim.x + threadIdx.x;
    if (idx < NCTA * 32 * HH) {                     // recurrent W, k-permuted
        int k = idx & (HH - 1);
        int l = (idx >> 10) & 31;
        int cta = idx >> 15;
        int g = (l >> 3) & 3;
        int j = cta * 8 + (l & 7);
        const float* W = (g == 0) ? Whf : (g == 1) ? Whi : (g == 2) ? Who : Whc;
        g_Wp[idx] = __float2half_rn(W[(size_t)permk(k) * HH + j]);
    }
    if (idx < NG * NIN) {                           // input W^T, natural
        int k = idx & (NIN - 1);
        int l = idx >> 9;
        int g = (l >> 3) & 3;
        int j = (l >> 5) * 8 + (l & 7);
        const float* W = (g == 0) ? Wuf : (g == 1) ? Wui : (g == 2) ? Wuo : Wuc;
        g_WuT[idx] = __float2half_rn(W[(size_t)k * HH + j]);
    }
}

__global__ void pack_B(const float* __restrict__ u, const float* __restrict__ Why,
                       const float* __restrict__ h0)
{
    long long idx = (long long)blockIdx.x * blockDim.x + threadIdx.x;
    if (idx < (long long)BB * TT * NIN) {
        int n = (int)(idx & (NIN - 1));
        int t = (int)((idx >> 9) & (TT - 1));
        int b = (int)(idx >> 19);
        g_u16[((size_t)t * BB + b) * NIN + n] = __float2half_rn(u[idx]);
    }
    if (idx < NOUT * HH) {
        int n = (int)idx / HH, k = (int)idx % HH;
        g_Wy[idx] = __float2half_rn(Why[(size_t)k * NOUT + n]);
    }
    if (idx < BB * HH) {
        g_histx[idx] = __float2half_rn(h0[idx & (HH - 1)]);
    }
    if (idx < (TT + 1) * 16) {
        g_flag[idx] = (idx < 16) ? 8u : 0u;
    }
}

// ---------------- X GEMM: X[t][l][b] = sum_k WuT[l][k]*u[t][b][k] + bias[l] ----------------
__global__ void __launch_bounds__(256, 2)
xgemm_kernel(const float* __restrict__ bf, const float* __restrict__ bi,
             const float* __restrict__ bo, const float* __restrict__ bc)
{
    extern __shared__ char sm[];
    __half* As = (__half*)sm;                 // [128 l][72]
    __half* Bs = (__half*)sm + 128 * 72;      // [128 b][72]
    const unsigned asb = smem_u32(As), bsb = smem_u32(Bs);

    const int tid = threadIdx.x, w = tid >> 5, lane = tid & 31;
    const int gq = lane >> 2, tg = lane & 3;
    const int bx = blockIdx.x, t = blockIdx.y;
    const int i8 = lane & 7, sel = lane >> 3;
    const unsigned aLane = ((w * 16 + (lane & 15)) * 144) + ((lane >> 4) * 16);
    const unsigned bRowOff = ((((sel >> 1) & 1) * 8 + i8) * 144) + ((sel & 1) * 16);

    float acc[16][4];
    #pragma unroll
    for (int nt = 0; nt < 16; ++nt)
        #pragma unroll
        for (int e = 0; e < 4; ++e) acc[nt][e] = 0.0f;

    for (int kc = 0; kc < NIN; kc += 64) {
        #pragma unroll
        for (int p = 0; p < 4; ++p) {
            int row = p * 32 + (tid >> 3), c8 = tid & 7;
            *(uint4*)(As + row * 72 + c8 * 8) =
                *(const uint4*)(g_WuT + (size_t)(bx * 128 + row) * NIN + kc + c8 * 8);
            *(uint4*)(Bs + row * 72 + c8 * 8) =
                *(const uint4*)(g_u16 + ((size_t)t * BB + row) * NIN + kc + c8 * 8);
        }
        __syncthreads();
        #pragma unroll
        for (int ks = 0; ks < 4; ++ks) {
            unsigned a0, a1, a2, a3;
            LDSM4(a0, a1, a2, a3, asb + aLane + ks * 32);
            #pragma unroll
            for (int p = 0; p < 8; ++p) {
                unsigned r0, r1, r2, r3;
                LDSM4(r0, r1, r2, r3, bsb + p * (16 * 144) + bRowOff + ks * 32);
                mma16816(acc[p * 2 + 0], a0, a1, a2, a3, r0, r1);
                mma16816(acc[p * 2 + 1], a0, a1, a2, a3, r2, r3);
            }
        }
        __syncthreads();
    }

    const float* bsel[4] = {bf, bi, bo, bc};
    #pragma unroll
    for (int rr = 0; rr < 2; ++rr) {
        int l = bx * 128 + w * 16 + gq + rr * 8;
        int g = (l >> 3) & 3;
        float bv = bsel[g][(l >> 5) * 8 + (l & 7)];
        float* orow = g_X + ((size_t)t * NG + l) * BB;
        #pragma unroll
        for (int nt = 0; nt < 16; ++nt) {
            float2 v = make_float2(acc[nt][rr * 2] + bv, acc[nt][rr * 2 + 1] + bv);
            *(float2*)(orow + nt * 8 + tg * 2) = v;
        }
    }
}

// ---------------- persistent recurrent kernel ----------------
// 8 MMA warps. LDG.128 A-frags from natural h (W k-permuted); LDSM hoisted per
// chunk; lookahead-2 data prefetch. Flag acquire-loads are themselves software-
// pipelined 4 chunks ahead (FV ring) so the fast path is a register compare.
// No __syncthreads in the step loop: SMEM arrival counter + single global release.
__global__ void __launch_bounds__(256, 1)
lstm_main(const float* __restrict__ h0)
{
    extern __shared__ char sm[];
    const unsigned smb = smem_u32(sm);
    const unsigned cntAddr = smb + WBYTES;
    const int tid = threadIdx.x, cta = blockIdx.x;
    const int w = tid >> 5, lane = tid & 31;
    const int gq = lane >> 2, tg = lane & 3;
    const int i8 = lane & 7, sel = lane >> 3;
    const unsigned bRowOff = ((((sel >> 1) & 1) * 8 + i8) * (WSTRIDE * 2)) + ((sel & 1) * 16);
    const int bb0 = w * 16 + gq;               // batch rows bb0, bb0+8
    const int j0  = cta * 8 + tg * 2;          // hidden cols (natural)
    const int c0  = cta >> 3;

    // resident recurrent W slice [32][1024] -> stride 1032 (k-permuted image)
    {
        const uint4* src = (const uint4*)(g_Wp + (size_t)cta * 32 * HH);
        for (int i = tid; i < 32 * 128; i += 256) {
            int r = i >> 7, c = i & 127;
            *(uint4*)((__half*)sm + r * WSTRIDE + c * 8) = src[(size_t)r * 128 + c];
        }
    }
    if (tid == 0) *(unsigned*)(sm + WBYTES) = 0u;
    __syncthreads();

    float hold[2][2];
    hold[0][0] = hold[1][0] = h0[j0];
    hold[0][1] = hold[1][1] = h0[j0 + 1];

    for (int t = 0; t < TT; ++t) {
        const char* r0p = (const char*)(g_histx + (size_t)t * BB * HH + (size_t)bb0 * HH) + tg * 16;
        const char* r8p = r0p + 8 * (HH * 2);
        const unsigned* fbase = &g_flag[t * 16];

        float acc[4][4];
        #pragma unroll
        for (int nt = 0; nt < 4; ++nt)
            #pragma unroll
            for (int e = 0; e < 4; ++e) acc[nt][e] = 0.0f;

        uint4 A[3][4];       // data ring (lookahead 2)
        unsigned FV[4];      // pipelined flag values (issued 4 chunks before test)
        float xr[16];

        // prologue: chunks 0,1 direct-wait + load; flag loads for chunks 2..5
        #pragma unroll
        for (int pi = 0; pi < 2; ++pi) {
            int c = (c0 + pi) & 15;
            wait_flag(fbase + c);
            const char* cb = r0p + c * 128;
            A[pi][0] = *(const uint4*)(cb);
            A[pi][1] = *(const uint4*)(r8p + c * 128);
            A[pi][2] = *(const uint4*)(cb + 64);
            A[pi][3] = *(const uint4*)(r8p + c * 128 + 64);
        }
        #pragma unroll
        for (int pf = 2; pf < 6; ++pf)
            FV[pf & 3] = flag_ld(fbase + ((c0 + pf) & 15));

        #pragma unroll
        for (int i = 0; i < NCHUNK; ++i) {
            if (i + 2 < NCHUNK) {
                int c = (c0 + i + 2) & 15;
                // fast path: register compare on the pipelined flag value
                if (FV[(i + 2) & 3] < 8u) wait_flag(fbase + c);
                uint4* Ap = A[(i + 2) % 3];
                const char* cb = r0p + c * 128;
                Ap[0] = *(const uint4*)(cb);
                Ap[1] = *(const uint4*)(r8p + c * 128);
                Ap[2] = *(const uint4*)(cb + 64);
                Ap[3] = *(const uint4*)(r8p + c * 128 + 64);
                if (i + 6 < NCHUNK)
                    FV[(i + 6) & 3] = flag_ld(fbase + ((c0 + i + 6) & 15));
            }
            if (i == 12) {
                // X preloads: ~3 chunks of MMA left to hide the L2 latency
                #pragma unroll
                for (int g = 0; g < 4; ++g)
                    #pragma unroll
                    for (int cc = 0; cc < 2; ++cc)
                        #pragma unroll
                        for (int rr = 0; rr < 2; ++rr)
                            xr[g * 4 + cc * 2 + rr] =
                                g_X[((size_t)t * NG + cta * 32 + g * 8 + tg * 2 + cc) * BB + bb0 + rr * 8];
            }
            const uint4* Ac = A[i % 3];
            const unsigned kb = smb + bRowOff + (unsigned)(((c0 + i) & 15) * 128);

            unsigned br[4][4], bs[4][4];
            #pragma unroll
            for (int ks = 0; ks < 4; ++ks)
                LDSM4(br[ks][0], br[ks][1], br[ks][2], br[ks][3], kb + ks * 32);
            #pragma unroll
            for (int ks = 0; ks < 4; ++ks)
                LDSM4(bs[ks][0], bs[ks][1], bs[ks][2], bs[ks][3],
                      kb + 16 * (WSTRIDE * 2) + ks * 32);

            #pragma unroll
            for (int ks = 0; ks < 4; ++ks) {
                const uint4 q0 = Ac[(ks >> 1) * 2], q8 = Ac[(ks >> 1) * 2 + 1];
                unsigned a0, a1, a2, a3;
                if ((ks & 1) == 0) { a0 = q0.x; a1 = q8.x; a2 = q0.y; a3 = q8.y; }
                else               { a0 = q0.z; a1 = q8.z; a2 = q0.w; a3 = q8.w; }
                mma16816(acc[0], a0, a1, a2, a3, br[ks][0], br[ks][1]);
                mma16816(acc[1], a0, a1, a2, a3, br[ks][2], br[ks][3]);
                mma16816(acc[2], a0, a1, a2, a3, bs[ks][0], bs[ks][1]);
                mma16816(acc[3], a0, a1, a2, a3, bs[ks][2], bs[ks][3]);
            }
        }

        // epilogue: gates (n-tiles are the 4 gates), register h_old, natural store
        __half* hw = g_histx + (size_t)(t + 1) * BB * HH;
        #pragma unroll
        for (int rr = 0; rr < 2; ++rr) {
            float hn[2];
            #pragma unroll
            for (int cc = 0; cc < 2; ++cc) {
                int e = rr * 2 + cc;
                float f  = siga (acc[0][e] + xr[0 * 4 + cc * 2 + rr]);
                float ii = siga (acc[1][e] + xr[1 * 4 + cc * 2 + rr]);
                float o  = siga (acc[2][e] + xr[2 * 4 + cc * 2 + rr]);
                float ct = tanha(acc[3][e] + xr[3 * 4 + cc * 2 + rr]);
                float cn = f * hold[rr][cc] + ii * ct;     // faithful: uses h, not c
                hn[cc] = o * tanha(cn);
                hold[rr][cc] = hn[cc];
            }
            *(__half2*)(hw + (size_t)(bb0 + rr * 8) * HH + j0) = __floats2half2_rn(hn[0], hn[1]);
        }

        // decoupled arrival: 8th warp of this CTA fires the single global release
        __syncwarp();
        if (lane == 0) {
            unsigned old = smem_arrive(cntAddr);
            if (old == (unsigned)(t * 8 + 7))
                release_flag(&g_flag[(t + 1) * 16 + (cta >> 3)]);
        }
    }
}

// ---------------- output pass: y = softmax(hist @ Wy + by) ----------------
__global__ void __launch_bounds__(256, 1)
y_kernel(const float* __restrict__ by, float* __restrict__ out)
{
    extern __shared__ char sm[];
    __half* As = (__half*)sm;
    __half* Bs = (__half*)sm + BB * SAY;

    const int tid = threadIdx.x, w = tid >> 5, lane = tid & 31;
    const int gq = lane >> 2, tg = lane & 3;
    const int t = blockIdx.x;
    const size_t rowbase = (size_t)(t + 1) * BB;            // y_t from h[t+1]
    const int R1 = w * 16 + gq;

    float acc[32][4];
    #pragma unroll
    for (int nt = 0; nt < 32; ++nt)
        #pragma unroll
        for (int e = 0; e < 4; ++e) acc[nt][e] = 0.0f;

    for (int kc = 0; kc < HH; kc += 64) {
        #pragma unroll
        for (int p = 0; p < 4; ++p) {
            int row = p * 32 + (tid >> 3), c8 = tid & 7;
            *(uint4*)(As + row * SAY + c8 * 8) =
                *(const uint4*)(g_histx + (rowbase + row) * HH + kc + c8 * 8);
        }
        #pragma unroll
        for (int p = 0; p < 8; ++p) {
            int row = p * 32 + (tid >> 3), c8 = tid & 7;
            *(uint4*)(Bs + row * SAY + c8 * 8) =
                *(const uint4*)(g_Wy + (size_t)row * HH + kc + c8 * 8);
        }
        __syncthreads();
        #pragma unroll
        for (int ks = 0; ks < 64; ks += 16) {
            const __half* Ap = As + R1 * SAY + ks + tg * 2;
            unsigned a0 = *(const unsigned*)(Ap);
            unsigned a1 = *(const unsigned*)(Ap + 8 * SAY);
            unsigned a2 = *(const unsigned*)(Ap + 8);
            unsigned a3 = *(const unsigned*)(Ap + 8 * SAY + 8);
            #pragma unroll
            for (int nt = 0; nt < 32; ++nt) {
                const __half* Bp = Bs + (nt * 8 + gq) * SAY + ks + tg * 2;
                mma16816(acc[nt], a0, a1, a2, a3,
                         *(const unsigned*)(Bp), *(const unsigned*)(Bp + 8));
            }
        }
        __syncthreads();
    }

    #pragma unroll
    for (int rr = 0; rr < 2; ++rr) {
        float m = -1e30f;
        #pragma unroll
        for (int nt = 0; nt < 32; ++nt)
            #pragma unroll
            for (int c = 0; c < 2; ++c) {
                float v = acc[nt][rr * 2 + c] + __ldg(&by[nt * 8 + tg * 2 + c]);
                acc[nt][rr * 2 + c] = v;
                m = fmaxf(m, v);
            }
        m = fmaxf(m, __shfl_xor_sync(0xffffffffu, m, 1));
        m = fmaxf(m, __shfl_xor_sync(0xffffffffu, m, 2));
        float s = 0.0f;
        #pragma unroll
        for (int nt = 0; nt < 32; ++nt)
            #pragma unroll
            for (int c = 0; c < 2; ++c) {
                float e = __expf(acc[nt][rr * 2 + c] - m);
                acc[nt][rr * 2 + c] = e;
                s += e;
            }
        s += __shfl_xor_sync(0xffffffffu, s, 1);
        s += __shfl_xor_sync(0xffffffffu, s, 2);
        float inv = 1.0f / s;
        int b = R1 + rr * 8;
        float* orow = out + ((size_t)b * TT + t) * NOUT;
        #pragma unroll
        for (int nt = 0; nt < 32; ++nt) {
            float2 pr = make_float2(acc[nt][rr * 2] * inv, acc[nt][rr * 2 + 1] * inv);
            *(float2*)(orow + nt * 8 + tg * 2) = pr;
        }
    }
}

// ---------------- launcher ----------------
extern "C" void kernel_launch(void* const* d_in, const int* in_sizes, int n_in,
                              void* d_out, int out_size)
{
    const float* u   = (const float*)d_in[0];
    const float* Wuf = (const float*)d_in[1];
    const float* Wui = (const float*)d_in[2];
    const float* Wuo = (const float*)d_in[3];
    const float* Wuc = (const float*)d_in[4];
    const float* Whf = (const float*)d_in[5];
    const float* Whi = (const float*)d_in[6];
    const float* Who = (const float*)d_in[7];
    const float* Whc = (const float*)d_in[8];
    const float* Why = (const float*)d_in[9];
    const float* bf  = (const float*)d_in[10];
    const float* bi  = (const float*)d_in[11];
    const float* bo  = (const float*)d_in[12];
    const float* bc  = (const float*)d_in[13];
    const float* by  = (const float*)d_in[14];
    const float* h0  = (const float*)d_in[15];
    float* out = (float*)d_out;

    cudaFuncSetAttribute(lstm_main, cudaFuncAttributeMaxDynamicSharedMemorySize, SMEM_MAIN);
    cudaFuncSetAttribute(y_kernel,  cudaFuncAttributeMaxDynamicSharedMemorySize, SMEM_Y);

    // 5 kernel nodes; lstm_main is the 4th (the node ncu's -s/-c window captures)
    pack_A<<<(NCTA * 32 * HH) / 256, 256>>>(Whf, Whi, Who, Whc, Wuf, Wui, Wuo, Wuc);
    pack_B<<<(int)(((long long)BB * TT * NIN) / 256), 256>>>(u, Why, h0);
    xgemm_kernel<<<dim3(NG / 128, TT), 256, XG_SMEM>>>(bf, bi, bo, bc);
    lstm_main<<<NCTA, 256, SMEM_MAIN>>>(h0);
    y_kernel<<<TT, 256, SMEM_Y>>>(by, out);
}